// round 8
// baseline (speedup 1.0000x reference)
#include <cuda_runtime.h>
#include <math.h>

// ---------------------------------------------------------------------------
// Marching tetrahedra on an implicit regular Kuhn tet grid (DMTetGeometry).
// Output (float32, concatenated): verts[E,3], faces[F,3], uvs[N*N*4,2],
// uv_idx[F,3].
//
// K0: streaming pos = verts + scale*tanh(deform); occ bytes
// K1: per-vertex crossing mask + lookback scan + vertex emit (packs
//     (edgebase<<8)|mask) ; ALSO per-cube tet codes + atomic n1/n2 totals
// K3: per-CUBE fused (m1,m2) lookback scan + face & uv_idx emission
// K4: constant uvs section (2D grid, no divisions, float4 when aligned)
// ---------------------------------------------------------------------------

#define MAXV 274625              // (64+1)^3
#define MAXC 262144              // 64^3 cubes
#define NT1MAX 1024
#define NT3MAX 2048
#define M21  ((1ull << 21) - 1ull)
#define M62  ((1ull << 62) - 1ull)

__device__ float              g_pos[3 * MAXV];
__device__ unsigned char      g_occ[MAXV];
__device__ unsigned           g_bm[MAXV];            // (edge base<<8) | mask
__device__ unsigned           g_ccode[MAXC];         // 6 codes x 4 bits
__device__ unsigned long long g_state[NT1MAX + NT3MAX]; // lookback (memset 0)
__device__ unsigned           g_small[8];            // [0,1]=tickets [2]=n1 [3]=n2 [4]=E

__constant__ int c_tri_table[16][6] = {
    {-1,-1,-1,-1,-1,-1},{1,0,2,-1,-1,-1},{4,0,3,-1,-1,-1},{1,4,2,1,3,4},
    {3,1,5,-1,-1,-1},{2,3,0,2,5,3},{1,4,0,1,5,4},{4,2,5,-1,-1,-1},
    {4,5,2,-1,-1,-1},{4,1,0,4,5,1},{3,2,0,3,5,2},{1,3,5,-1,-1,-1},
    {4,1,2,4,3,1},{3,0,4,-1,-1,-1},{2,0,1,-1,-1,-1},{-1,-1,-1,-1,-1,-1}};
__constant__ int c_num_tri[16] = {0,1,1,2,1,2,2,1,1,2,2,1,2,1,1,0};
__constant__ int c_kuhn[6][4]  = {{0,1,3,7},{0,2,3,7},{0,1,5,7},
                                  {0,2,6,7},{0,4,5,7},{0,4,6,7}};
// For tet k, tet-edge e (pairs (0,1),(0,2),(0,3),(1,2),(1,3),(2,3)):
// value = (min cube corner)<<3 | lattice dir.  dir = 4dx+2dy+dz-1, matching
// the mask-bit order of deltas {1,S,S+1,S2,S2+1,S2+S,S2+S+1}.
__constant__ unsigned char c_einfo[6][6] = {
    { 3, 5, 6,  9, 10, 24},   // tet0 {0,1,3,7}
    { 1, 5, 6, 19, 20, 24},   // tet1 {0,2,3,7}
    { 3, 4, 6,  8, 10, 41},   // tet2 {0,1,5,7}
    { 1, 2, 6, 16, 20, 51},   // tet3 {0,2,6,7}
    { 0, 4, 6, 35, 37, 41},   // tet4 {0,4,5,7}
    { 0, 2, 6, 33, 37, 51}};  // tet5 {0,4,6,7}

// ===========================================================================
// K0: deformed positions (streaming) + occupancy bytes
// ===========================================================================
__global__ void __launch_bounds__(256)
k0_pos_occ(const float* __restrict__ verts, const float* __restrict__ deform,
           const float* __restrict__ sdf, int Nv, float scale) {
    int i = blockIdx.x * blockDim.x + threadIdx.x;
    if (i < 3 * Nv)
        g_pos[i] = verts[i] + scale * tanhf(deform[i]);
    if (i < Nv)
        g_occ[i] = (unsigned char)(sdf[i] > 0.0f);
}

// ===========================================================================
// K1: crossing mask + lookback scan + vertex emission (+ cube codes/totals)
//     1 vertex / thread, 512-thread blocks
// ===========================================================================
__global__ void __launch_bounds__(512)
k1_mask_scan_emit(const float* __restrict__ sdf, float* __restrict__ out,
                  int S, int Nv, int R, int C, int ntiles) {
    __shared__ unsigned s_tile;
    __shared__ unsigned s_wex[16];
    __shared__ unsigned s_bex;
    if (threadIdx.x == 0) s_tile = atomicAdd(&g_small[0], 1u);
    __syncthreads();
    int tile = (int)s_tile;
    int a = tile * 512 + threadIdx.x;
    int S2 = S * S;
    int d[7] = {1, S, S + 1, S2, S2 + 1, S2 + S, S2 + S + 1};

    // ---- per-cube tet codes + (n1,n2) totals (independent work) ----
    {
        int c = a;
        unsigned cnt1 = 0, cnt2 = 0;
        if (c < C) {
            int cz = c % R;
            int cy = (c / R) % R;
            int cx = c / (R * R);
            int v000 = (cx * S + cy) * S + cz;
            int coff[8] = {0, S2, S, S2 + S, 1, S2 + 1, S + 1, S2 + S + 1};
            unsigned ob[8];
            #pragma unroll
            for (int i = 0; i < 8; i++) ob[i] = (unsigned)g_occ[v000 + coff[i]];
            unsigned packed = 0;
            #pragma unroll
            for (int k = 0; k < 6; k++) {
                unsigned code = ob[c_kuhn[k][0]] | (ob[c_kuhn[k][1]] << 1)
                              | (ob[c_kuhn[k][2]] << 2) | (ob[c_kuhn[k][3]] << 3);
                packed |= code << (4 * k);
                int nt = c_num_tri[code];
                cnt1 += (nt == 1);
                cnt2 += (nt == 2);
            }
            g_ccode[c] = packed;
        }
        // warp reduce then one atomic pair per warp
        #pragma unroll
        for (int off = 16; off > 0; off >>= 1) {
            cnt1 += __shfl_down_sync(0xffffffffu, cnt1, off);
            cnt2 += __shfl_down_sync(0xffffffffu, cnt2, off);
        }
        if ((threadIdx.x & 31) == 0) {
            if (cnt1) atomicAdd(&g_small[2], cnt1);
            if (cnt2) atomicAdd(&g_small[3], cnt2);
        }
    }

    // ---- crossing mask ----
    unsigned m = 0;
    if (a < Nv) {
        int z = a % S;
        int y = (a / S) % S;
        int x = a / S2;
        unsigned oa = g_occ[a];
        bool ok[7] = { z < R, y < R, (y < R && z < R), x < R,
                       (x < R && z < R), (x < R && y < R),
                       (x < R && y < R && z < R) };
        #pragma unroll
        for (int k = 0; k < 7; k++)
            if (ok[k] && ((unsigned)g_occ[a + d[k]] != oa)) m |= (1u << k);
    }
    unsigned cnt = (unsigned)__popc(m);

    // ---- block exclusive scan (512 threads) ----
    int lane = threadIdx.x & 31, wid = threadIdx.x >> 5;
    unsigned inc = cnt;
    #pragma unroll
    for (int off = 1; off < 32; off <<= 1) {
        unsigned n = __shfl_up_sync(0xffffffffu, inc, off);
        if (lane >= off) inc += n;
    }
    if (lane == 31) s_wex[wid] = inc;
    __syncthreads();
    if (threadIdx.x == 0) {
        unsigned run = 0;
        #pragma unroll
        for (int w = 0; w < 16; w++) { unsigned t = s_wex[w]; s_wex[w] = run; run += t; }
        unsigned long long agg = run;
        unsigned long long bex = 0;
        if (tile == 0) {
            atomicExch(&g_state[0], (2ull << 62) | agg);
        } else {
            atomicExch(&g_state[tile], (1ull << 62) | agg);
            unsigned long long sum = 0;
            int i = tile - 1;
            while (true) {
                unsigned long long v;
                do { v = *((volatile unsigned long long*)&g_state[i]); } while ((v >> 62) == 0ull);
                sum += v & M62;
                if ((v >> 62) == 2ull) break;
                i--;
            }
            bex = sum;
            atomicExch(&g_state[tile], (2ull << 62) | (bex + agg));
        }
        s_bex = (unsigned)bex;
        if (tile == ntiles - 1) g_small[4] = (unsigned)(bex + agg);
    }
    __syncthreads();
    unsigned ebase = s_bex + s_wex[wid] + (inc - cnt);

    if (a >= Nv) return;
    g_bm[a] = (ebase << 8) | m;
    if (!m) return;

    // ---- emit interpolated surface vertices ----
    float s0  = sdf[a];
    float pax = g_pos[3 * a + 0];
    float pay = g_pos[3 * a + 1];
    float paz = g_pos[3 * a + 2];
    unsigned idx = ebase;
    #pragma unroll
    for (int k = 0; k < 7; k++) {
        if ((m >> k) & 1u) {
            int b = a + d[k];
            float s1 = sdf[b];
            float denom = s0 - s1;
            float w0 = -s1 / denom;
            float w1 =  s0 / denom;
            out[3 * idx + 0] = pax * w0 + g_pos[3 * b + 0] * w1;
            out[3 * idx + 1] = pay * w0 + g_pos[3 * b + 1] * w1;
            out[3 * idx + 2] = paz * w0 + g_pos[3 * b + 2] * w1;
            idx++;
        }
    }
}

// ===========================================================================
// K3: per-cube fused (m1,m2) lookback scan + face & uv_idx emission
//     1 cube / thread, 256-thread blocks
// ===========================================================================
__global__ void __launch_bounds__(256)
k3_faces(float* __restrict__ out, int R, int S, int C, int ntiles,
         int state_off, unsigned uvlen) {
    __shared__ unsigned s_tile;
    __shared__ unsigned long long s_wex[8];
    __shared__ unsigned long long s_bex;
    if (threadIdx.x == 0) s_tile = atomicAdd(&g_small[1], 1u);
    __syncthreads();
    int tile = (int)s_tile;
    int c = tile * 256 + threadIdx.x;

    unsigned codes = (c < C) ? g_ccode[c] : 0u;
    unsigned long long cnt = 0;
    #pragma unroll
    for (int k = 0; k < 6; k++) {
        int code = (int)((codes >> (4 * k)) & 15u);
        int nt = c_num_tri[code];
        if (nt == 1)      cnt += 1ull;
        else if (nt == 2) cnt += (1ull << 21);
    }

    // block exclusive scan (u64, two 21-bit fields)
    int lane = threadIdx.x & 31, wid = threadIdx.x >> 5;
    unsigned long long inc = cnt;
    #pragma unroll
    for (int off = 1; off < 32; off <<= 1) {
        unsigned long long n = __shfl_up_sync(0xffffffffu, inc, off);
        if (lane >= off) inc += n;
    }
    if (lane == 31) s_wex[wid] = inc;
    __syncthreads();
    if (threadIdx.x == 0) {
        unsigned long long run = 0;
        #pragma unroll
        for (int w = 0; w < 8; w++) { unsigned long long t = s_wex[w]; s_wex[w] = run; run += t; }
        unsigned long long agg = run;
        unsigned long long bex = 0;
        unsigned long long* st = g_state + state_off;
        if (tile == 0) {
            atomicExch(&st[0], (2ull << 62) | agg);
        } else {
            atomicExch(&st[tile], (1ull << 62) | agg);
            unsigned long long acc = 0;
            int i = tile - 1;
            while (true) {
                unsigned long long v;
                do { v = *((volatile unsigned long long*)&st[i]); } while ((v >> 62) == 0ull);
                acc += v & M62;
                if ((v >> 62) == 2ull) break;
                i--;
            }
            bex = acc;
            atomicExch(&st[tile], (2ull << 62) | (bex + agg));
        }
        s_bex = bex;
    }
    __syncthreads();
    if (c >= C || cnt == 0ull) return;

    unsigned long long pre = s_bex + s_wex[wid] + (inc - cnt);
    unsigned m1e = (unsigned)(pre & M21);
    unsigned m2e = (unsigned)((pre >> 21) & M21);

    unsigned E  = g_small[4];
    unsigned n1 = g_small[2];
    unsigned n2 = g_small[3];
    unsigned fbase   = 3u * E;
    unsigned uvibase = 3u * E + 3u * (n1 + 2u * n2) + uvlen;

    int cz = c % R;
    int cy = (c / R) % R;
    int cx = c / (R * R);
    int S2 = S * S;
    int v000 = (cx * S + cy) * S + cz;
    int coff[8] = {0, S2, S, S2 + S, 1, S2 + 1, S + 1, S2 + S + 1};
    unsigned bm[8];
    #pragma unroll
    for (int i = 0; i < 8; i++) bm[i] = g_bm[v000 + coff[i]];

    float tbase = (float)(24u * (unsigned)c);   // 4 * (6c)

    #pragma unroll
    for (int k = 0; k < 6; k++) {
        int code = (int)((codes >> (4 * k)) & 15u);
        int nt = c_num_tri[code];
        if (nt == 0) continue;
        float tg4 = tbase + (float)(4 * k);
        if (nt == 1) {
            unsigned row = m1e++;
            float* fp = out + fbase + 3u * row;
            #pragma unroll
            for (int j = 0; j < 3; j++) {
                int e = c_tri_table[code][j];
                unsigned info = c_einfo[k][e];
                unsigned b = bm[info >> 3];
                unsigned dir = info & 7u;
                fp[j] = (float)((b >> 8) + (unsigned)__popc(b & ((1u << dir) - 1u)));
            }
            float* up = out + uvibase + 3u * row;
            up[0] = tg4; up[1] = tg4 + 1.0f; up[2] = tg4 + 2.0f;
        } else {
            unsigned row0 = n1 + 2u * (m2e++);
            float* fp = out + fbase + 3u * row0;
            #pragma unroll
            for (int j = 0; j < 6; j++) {
                int e = c_tri_table[code][j];
                unsigned info = c_einfo[k][e];
                unsigned b = bm[info >> 3];
                unsigned dir = info & 7u;
                fp[j] = (float)((b >> 8) + (unsigned)__popc(b & ((1u << dir) - 1u)));
            }
            float* up = out + uvibase + 3u * row0;
            up[0] = tg4; up[1] = tg4 + 1.0f; up[2] = tg4 + 2.0f;
            up[3] = tg4; up[4] = tg4 + 2.0f; up[5] = tg4 + 3.0f;
        }
    }
}

// ===========================================================================
// K4: constant uvs section.  2D grid: blockIdx.y = row (iy), no divisions.
// ===========================================================================
__global__ void __launch_bounds__(256)
k4_uvs(float* __restrict__ out, int N, float delta, float pad) {
    int ix = blockIdx.x * blockDim.x + threadIdx.x;
    if (ix >= N) return;
    int iy = blockIdx.y;
    unsigned E  = g_small[4];
    unsigned F  = g_small[2] + 2u * g_small[3];
    unsigned ub = 3u * E + 3u * F;
    float x = (float)ix * delta;
    float y = (float)iy * delta;
    float xp = x + pad, yp = y + pad;
    unsigned o = ub + 8u * ((unsigned)iy * (unsigned)N + (unsigned)ix);
    if ((ub & 3u) == 0u) {
        float4* p = (float4*)(out + o);
        p[0] = make_float4(x, y, xp, y);
        p[1] = make_float4(xp, yp, x, yp);
    } else {
        float* p = out + o;
        p[0] = x;  p[1] = y;
        p[2] = xp; p[3] = y;
        p[4] = xp; p[5] = yp;
        p[6] = x;  p[7] = yp;
    }
}

// ---------------------------------------------------------------------------
extern "C" void kernel_launch(void* const* d_in, const int* in_sizes, int n_in,
                              void* d_out, int out_size) {
    const float* verts  = (const float*)d_in[0];
    const float* sdf    = (const float*)d_in[1];
    const float* deform = (const float*)d_in[2];
    float* out = (float*)d_out;

    int Nv = in_sizes[1];                 // (R+1)^3
    int S = 1;
    while (S * S * S < Nv) S++;
    int R = S - 1;
    int C = R * R * R;                    // cubes
    long T = (long)in_sizes[3] / 4;       // tet count = 6*C

    int N = (int)sqrt((double)T);         // N = ceil(sqrt(T))
    while ((long)N * N < T) N++;

    float stopf = (float)(1.0 - 1.0 / (double)N);
    float delta = stopf / (float)(N - 1);
    float pad   = (float)(0.9 / (double)N);
    float scale = 2.0f / (float)(R * 2);
    unsigned uvlen = 8u * (unsigned)N * (unsigned)N;

    int nt1 = (Nv + 511) / 512;           // K1 tiles
    int nt3 = (C + 255) / 256;            // K3 tiles

    void *p_state, *p_small;
    cudaGetSymbolAddress(&p_state, g_state);
    cudaGetSymbolAddress(&p_small, g_small);

    cudaMemsetAsync(p_state, 0, (size_t)(nt1 + nt3) * sizeof(unsigned long long));
    cudaMemsetAsync(p_small, 0, 8 * sizeof(unsigned));

    // K0: pos + occ (streaming)
    int g0 = (3 * Nv + 255) / 256;
    k0_pos_occ<<<g0, 256>>>(verts, deform, sdf, Nv, scale);

    // K1: mask + scan + vertex emission + cube codes + totals
    k1_mask_scan_emit<<<nt1, 512>>>(sdf, out, S, Nv, R, C, nt1);

    // K3: per-cube fused scan + faces + uv_idx
    k3_faces<<<nt3, 256>>>(out, R, S, C, nt3, nt1, uvlen);

    // K4: uvs (2D grid: x over columns, y over rows)
    dim3 g4((N + 255) / 256, N);
    k4_uvs<<<g4, 256>>>(out, N, delta, pad);
}